// round 14
// baseline (speedup 1.0000x reference)
#include <cuda_runtime.h>
#include <cstdint>
#include <cstddef>

#define BATCH 8192
#define INF   784
#define HID   4096
#define OUTF  10
#define KP    832            // 13 chunks of 64
#define NCH   13

#define TMT 128
#define TNT 128
#define NTHR 544             // 16 consumer warps + 1 producer warp

// x = a1/16 + a2/4064 + eps, |eps| <= 1/8128
#define S1_INV 0.0625f
#define S2_INV (1.0f / 4064.0f)

// chunk-major gmem blocks
#define CHUNK_A (BATCH * 64)
#define CHUNK_B (HID * 64)

// SMEM: 4 stages x (Ahi 8K | Alo 8K | B 8K) = 98304
#define STAGE_B  24576u
#define NSTG     4
#define SOFF_QB  69632u              // [4][128][10] f32 quarter partials (reuses stage rgn)
#define SOFF_W2  98304u              // [10][128] f32
#define SOFF_B1  103424u             // [128] f32
#define SOFF_FBAR 103936u            // full[4]
#define SOFF_EBAR 103968u            // empty[4]
#define SOFF_LAST 104000u            // 4B "am I last" flag
#define SMEM_DYN 104960u

// consumer-only named barrier (16 warps = 512 threads)
#define CONS_BAR() asm volatile("bar.sync 1, 512;" ::: "memory")

// ---------------------------------------------------------------------------
__device__ signed char g_A8c[2ull * NCH * CHUNK_A];
__device__ signed char g_S8c[(size_t)NCH * CHUNK_B];
__device__ float g_part[32ull * BATCH * OUTF];
__device__ unsigned int g_cnt[BATCH / TMT];   // per-m-tile arrival counters

// ---------------------------------------------------------------------------
__device__ __forceinline__ uint32_t smem_u32(const void* p) {
    uint32_t a;
    asm("{ .reg .u64 t; cvta.to.shared.u64 t, %1; cvt.u32.u64 %0, t; }"
        : "=r"(a) : "l"(p));
    return a;
}

__device__ __forceinline__ uint32_t chunk_off(int row, int kk) {
    uint32_t line = (uint32_t)(row >> 1);
    uint32_t col  = (((uint32_t)(row & 1)) << 6) | (uint32_t)kk;
    return (line << 7) | (col ^ ((line & 7u) << 4));
}

__device__ __forceinline__ void ldsm_x4(uint32_t& r0, uint32_t& r1,
                                        uint32_t& r2, uint32_t& r3, uint32_t a) {
    asm volatile("ldmatrix.sync.aligned.m8n8.x4.shared.b16 {%0,%1,%2,%3}, [%4];"
                 : "=r"(r0), "=r"(r1), "=r"(r2), "=r"(r3) : "r"(a));
}

__device__ __forceinline__ void mma_s8(int* d, uint32_t a0, uint32_t a1,
                                       uint32_t a2, uint32_t a3,
                                       uint32_t b0, uint32_t b1) {
    asm volatile(
        "mma.sync.aligned.m16n8k32.row.col.s32.s8.s8.s32 "
        "{%0,%1,%2,%3}, {%4,%5,%6,%7}, {%8,%9}, {%0,%1,%2,%3};"
        : "+r"(d[0]), "+r"(d[1]), "+r"(d[2]), "+r"(d[3])
        : "r"(a0), "r"(a1), "r"(a2), "r"(a3), "r"(b0), "r"(b1));
}

#define MBAR_INIT(a, c) \
    asm volatile("mbarrier.init.shared.b64 [%0], %1;" :: "r"(a), "r"(c) : "memory")
#define MBAR_EXPECT(a, bytes) \
    asm volatile("mbarrier.arrive.expect_tx.shared.b64 _, [%0], %1;" \
                 :: "r"(a), "r"(bytes) : "memory")
#define MBAR_ARRIVE(a) \
    asm volatile("mbarrier.arrive.shared.b64 _, [%0];" :: "r"(a) : "memory")
#define BULK_CP(dst, src, size, mbar) \
    asm volatile("cp.async.bulk.shared::cluster.global.mbarrier::complete_tx::bytes " \
                 "[%0], [%1], %2, [%3];" \
                 :: "r"(dst), "l"(src), "r"(size), "r"(mbar) : "memory")

#define MBAR_WAIT(a, par) do {                                                 \
    uint32_t _m = (a), _p = (par), _d;                                         \
    asm volatile("{\n\t.reg .pred p;\n\t"                                      \
        "mbarrier.try_wait.parity.acquire.cta.shared::cta.b64 p, [%1], %2;\n\t"\
        "selp.b32 %0, 1, 0, p;\n\t}" : "=r"(_d) : "r"(_m), "r"(_p) : "memory");\
    if (!_d) {                                                                 \
        asm volatile("{\n\t.reg .pred P1;\n\t"                                 \
            "WL_%=:\n\t"                                                       \
            "mbarrier.try_wait.parity.acquire.cta.shared::cta.b64 P1, [%0], %1, 0x989680;\n\t" \
            "@P1 bra.uni WD_%=;\n\t"                                           \
            "bra.uni WL_%=;\n\t"                                               \
            "WD_%=:\n\t}" :: "r"(_m), "r"(_p) : "memory");                     \
    }                                                                          \
} while (0)

// ---------------------------------------------------------------------------
// Fused prep, warp-coalesced stores: thread index = ((c*ROWS + r)*4 + t4),
// so one warp covers 8 consecutive rows x 4 k16-segments of ONE chunk ->
// its 16B swizzled stores form one contiguous 512B block per plane.
// ---------------------------------------------------------------------------
#define XT (NCH * BATCH * 4)
#define WT (NCH * HID * 4)

__global__ void prep_kernel(const float* __restrict__ x,
                            const float* __restrict__ W1) {
    int idx = blockIdx.x * blockDim.x + threadIdx.x;
    if (idx < XT) {
        const int c  = idx / (BATCH * 4);
        const int rm = idx - c * (BATCH * 4);
        const int m  = rm >> 2;
        const int t4 = rm & 3;
        const int k16 = c * 64 + t4 * 16;
        uint4 p1 = make_uint4(0u, 0u, 0u, 0u);
        uint4 p2 = make_uint4(0u, 0u, 0u, 0u);
        if (k16 < INF) {
            uint32_t* w1 = &p1.x;
            uint32_t* w2 = &p2.x;
            #pragma unroll
            for (int q = 0; q < 4; q++) {
                const float4 v = *reinterpret_cast<const float4*>(
                    x + m * INF + k16 + q * 4);
                const float* vv = &v.x;
                uint32_t b1w = 0, b2w = 0;
                #pragma unroll
                for (int j = 0; j < 4; j++) {
                    float a1 = rintf(vv[j] * 16.0f);
                    float r  = vv[j] - a1 * S1_INV;
                    float a2 = rintf(r * 4064.0f);
                    b1w |= ((uint32_t)(uint8_t)(signed char)(int)a1) << (j * 8);
                    b2w |= ((uint32_t)(uint8_t)(signed char)(int)a2) << (j * 8);
                }
                w1[q] = b1w;
                w2[q] = b2w;
            }
        }
        const size_t o = (size_t)c * CHUNK_A + chunk_off(m, t4 * 16);
        *reinterpret_cast<uint4*>(g_A8c + o) = p1;
        *reinterpret_cast<uint4*>(g_A8c + (size_t)NCH * CHUNK_A + o) = p2;
    } else if (idx < XT + WT) {
        const int j2 = idx - XT;
        const int c  = j2 / (HID * 4);
        const int rm = j2 - c * (HID * 4);
        const int r  = rm >> 2;
        const int t4 = rm & 3;
        const int k16 = c * 64 + t4 * 16;
        uint4 ps = make_uint4(0u, 0u, 0u, 0u);
        if (k16 < INF) {
            uint32_t* w = &ps.x;
            #pragma unroll
            for (int q = 0; q < 4; q++) {
                const float4 v = *reinterpret_cast<const float4*>(
                    W1 + r * INF + k16 + q * 4);
                const float* vv = &v.x;
                uint32_t bw = 0;
                #pragma unroll
                for (int j = 0; j < 4; j++) {
                    int s = (vv[j] > 0.0f) ? 1 : ((vv[j] < 0.0f) ? -1 : 0);
                    bw |= ((uint32_t)(uint8_t)(signed char)s) << (j * 8);
                }
                w[q] = bw;
            }
        }
        *reinterpret_cast<uint4*>(
            g_S8c + (size_t)c * CHUNK_B + chunk_off(r, t4 * 16)) = ps;
    }
}

// ---------------------------------------------------------------------------
// GEMM1: mainloop/epilogue identical to passing R13; final reduction fused —
// the 32nd CTA per m-tile (atomic counter, fixed p-loop order => deterministic)
// sums all slices + b2 and writes out directly.
// ---------------------------------------------------------------------------
__global__ __launch_bounds__(NTHR, 1)
void gemm1_kernel(const float* __restrict__ b1g, const float* __restrict__ W2g,
                  const float* __restrict__ b2g, float* __restrict__ outg) {
    extern __shared__ unsigned char smem[];
    float* Csh  = (float*)smem;                   // epilogue reuse of stages
    float* Qb   = (float*)(smem + SOFF_QB);       // [4][128][10]
    float* W2sh = (float*)(smem + SOFF_W2);
    float* b1sh = (float*)(smem + SOFF_B1);
    const uint32_t sb = smem_u32(smem);

    const int tid = threadIdx.x;
    const int wid = tid >> 5;
    const int lane = tid & 31;
    const int m0 = blockIdx.y * TMT;
    const int n0 = blockIdx.x * TNT;

    if (tid == 0) {
        #pragma unroll
        for (int s = 0; s < NSTG; s++) {
            MBAR_INIT(sb + SOFF_FBAR + s * 8, 1);    // producer expect_tx
            MBAR_INIT(sb + SOFF_EBAR + s * 8, 16);   // 16 consumer warps
        }
    }
    for (int i = tid; i < OUTF * 128; i += NTHR) {
        int o = i / 128, n = i - o * 128;
        W2sh[o * 128 + n] = W2g[o * HID + n0 + n];
    }
    if (tid < 128) b1sh[tid] = b1g[n0 + tid];
    __syncthreads();   // single, convergent CTA-wide sync

    // ---------------- producer warp: issue everything, then exit ----------
    if (wid == 16) {
        if (lane == 0) {
            for (int c = 0; c < NCH; c++) {
                const int s = c & 3;
                if (c >= NSTG)
                    MBAR_WAIT(sb + SOFF_EBAR + s * 8, ((c >> 2) + 1) & 1);
                const uint32_t stg = sb + (uint32_t)s * STAGE_B;
                const uint32_t mb  = sb + SOFF_FBAR + s * 8;
                MBAR_EXPECT(mb, STAGE_B);
                const signed char* a0 = g_A8c + (size_t)c * CHUNK_A + (size_t)m0 * 64;
                const signed char* a1 = g_A8c + (size_t)(NCH + c) * CHUNK_A + (size_t)m0 * 64;
                const signed char* bb = g_S8c + (size_t)c * CHUNK_B + (size_t)n0 * 64;
                BULK_CP(stg,          a0, 8192u, mb);
                BULK_CP(stg + 8192u,  a1, 8192u, mb);
                BULK_CP(stg + 16384u, bb, 8192u, mb);
            }
        }
        return;
    }

    // ---------------- consumers (512 threads) -----------------------------
    const int wm = wid & 3;
    const int wn = wid >> 2;
    const int l15 = lane & 15;

    uint32_t a_line[2][2], a_xm[2][2], a_c0[2][2];
    #pragma unroll
    for (int pl = 0; pl < 2; pl++)
        #pragma unroll
        for (int mf = 0; mf < 2; mf++) {
            int r = wm * 32 + mf * 16 + l15;
            a_line[pl][mf] = (uint32_t)pl * 8192u + (((uint32_t)r >> 1) << 7);
            a_xm[pl][mf]   = (((uint32_t)(r >> 1) & 7u) << 4);
            a_c0[pl][mf]   = (((uint32_t)r & 1u) << 6) | (((uint32_t)lane >> 4) << 4);
        }
    uint32_t b_line[2], b_xm[2], b_c0[2];
    #pragma unroll
    for (int np = 0; np < 2; np++) {
        int r = wn * 32 + np * 16 + ((lane >> 4) << 3) + (lane & 7);
        b_line[np] = 16384u + (((uint32_t)r >> 1) << 7);
        b_xm[np]   = (((uint32_t)(r >> 1) & 7u) << 4);
        b_c0[np]   = (((uint32_t)r & 1u) << 6) | ((((uint32_t)lane >> 3) & 1u) << 4);
    }

    int acc[2][2][4][4];
    #pragma unroll
    for (int pl = 0; pl < 2; pl++)
        #pragma unroll
        for (int mf = 0; mf < 2; mf++)
            #pragma unroll
            for (int n8 = 0; n8 < 4; n8++)
                #pragma unroll
                for (int e = 0; e < 4; e++) acc[pl][mf][n8][e] = 0;

    for (int c = 0; c < NCH; c++) {
        const int s = c & 3;
        MBAR_WAIT(sb + SOFF_FBAR + s * 8, (c >> 2) & 1);
        const uint32_t stg = sb + (uint32_t)s * STAGE_B;

        const int kbmax = (c == NCH - 1) ? 32 : 64;   // last chunk: k>=784 is zero
        #pragma unroll 2
        for (int kb = 0; kb < kbmax; kb += 32) {
            uint32_t b[8];
            ldsm_x4(b[0], b[1], b[2], b[3],
                    stg + b_line[0] + ((b_c0[0] + kb) ^ b_xm[0]));
            ldsm_x4(b[4], b[5], b[6], b[7],
                    stg + b_line[1] + ((b_c0[1] + kb) ^ b_xm[1]));
            #pragma unroll
            for (int pl = 0; pl < 2; pl++) {
                #pragma unroll
                for (int mf = 0; mf < 2; mf++) {
                    uint32_t a0, a1, a2, a3;
                    ldsm_x4(a0, a1, a2, a3,
                            stg + a_line[pl][mf] + ((a_c0[pl][mf] + kb) ^ a_xm[pl][mf]));
                    mma_s8(acc[pl][mf][0], a0, a1, a2, a3, b[0], b[1]);
                    mma_s8(acc[pl][mf][1], a0, a1, a2, a3, b[2], b[3]);
                    mma_s8(acc[pl][mf][2], a0, a1, a2, a3, b[4], b[5]);
                    mma_s8(acc[pl][mf][3], a0, a1, a2, a3, b[6], b[7]);
                }
            }
        }
        if (lane == 0) MBAR_ARRIVE(sb + SOFF_EBAR + s * 8);
    }

    CONS_BAR();   // all stages consumed; no bulk copies in flight -> reuse as Csh

    // ---- combine planes in registers, store h tile to smem ----
    {
        const int g  = lane >> 2;
        const int tg = lane & 3;
        #pragma unroll
        for (int mf = 0; mf < 2; mf++) {
            #pragma unroll
            for (int n8 = 0; n8 < 4; n8++) {
                const int* Ah = acc[0][mf][n8];
                const int* Al = acc[1][mf][n8];
                int row0 = wm * 32 + mf * 16 + g;
                int col  = wn * 32 + n8 * 8 + 2 * tg;
                Csh[row0 * 132 + col]           = (float)Ah[0] * S1_INV + (float)Al[0] * S2_INV;
                Csh[row0 * 132 + col + 1]       = (float)Ah[1] * S1_INV + (float)Al[1] * S2_INV;
                Csh[(row0 + 8) * 132 + col]     = (float)Ah[2] * S1_INV + (float)Al[2] * S2_INV;
                Csh[(row0 + 8) * 132 + col + 1] = (float)Ah[3] * S1_INV + (float)Al[3] * S2_INV;
            }
        }
    }
    CONS_BAR();

    // ---- bias + clip + W2 contraction; quarter partials in smem ----
    {
        const int row = tid & 127;
        const int q   = tid >> 7;          // 0..3
        float a[OUTF];
        #pragma unroll
        for (int o = 0; o < OUTF; o++) a[o] = 0.0f;

        const int nbeg = q * 32;
        #pragma unroll 4
        for (int n = nbeg; n < nbeg + 32; n++) {
            float h = Csh[row * 132 + n] + b1sh[n];
            h = fminf(1.0f, fmaxf(-1.0f, h));
            #pragma unroll
            for (int o = 0; o < OUTF; o++) a[o] += h * W2sh[o * 128 + n];
        }
        #pragma unroll
        for (int o = 0; o < OUTF; o++)
            Qb[(q * 128 + row) * OUTF + o] = a[o];
    }
    CONS_BAR();

    // ---- combine quarters, write one slice per CTA column ----
    for (int i = tid; i < 128 * OUTF; i += 512) {
        float s = Qb[i] + Qb[128 * OUTF + i] + Qb[256 * OUTF + i] + Qb[384 * OUTF + i];
        int row = i / OUTF, o = i - row * OUTF;
        g_part[((size_t)blockIdx.x * BATCH + m0 + row) * OUTF + o] = s;
    }
    CONS_BAR();   // slice fully written by all 512 threads

    // ---- fused final reduction: 32nd arriver per m-tile sums all slices ----
    if (tid == 0) {
        __threadfence();                             // publish slice writes
        unsigned int old = atomicAdd(&g_cnt[blockIdx.y], 1u);
        *(unsigned int*)(smem + SOFF_LAST) = ((old & 31u) == 31u) ? 1u : 0u;
    }
    CONS_BAR();
    if (*(unsigned int*)(smem + SOFF_LAST)) {
        __threadfence();                             // acquire other slices
        for (int i = tid; i < TMT * OUTF / 4; i += 512) {
            const size_t base = (size_t)m0 * OUTF + i * 4;
            float4 s = make_float4(0.f, 0.f, 0.f, 0.f);
            #pragma unroll
            for (int p = 0; p < 32; p++) {
                const float4 v = *reinterpret_cast<const float4*>(
                    g_part + (size_t)p * BATCH * OUTF + base);
                s.x += v.x; s.y += v.y; s.z += v.z; s.w += v.w;
            }
            const int j = i * 4;
            s.x += b2g[j % OUTF];
            s.y += b2g[(j + 1) % OUTF];
            s.z += b2g[(j + 2) % OUTF];
            s.w += b2g[(j + 3) % OUTF];
            *reinterpret_cast<float4*>(outg + base) = s;
        }
    }
}

// ---------------------------------------------------------------------------
extern "C" void kernel_launch(void* const* d_in, const int* in_sizes, int n_in,
                              void* d_out, int out_size) {
    (void)in_sizes; (void)n_in; (void)out_size;
    const float* x  = (const float*)d_in[0];
    const float* W1 = (const float*)d_in[1];
    const float* b1 = (const float*)d_in[2];
    const float* W2 = (const float*)d_in[3];
    const float* b2 = (const float*)d_in[4];
    float* out = (float*)d_out;

    cudaFuncSetAttribute(gemm1_kernel,
                         cudaFuncAttributeMaxDynamicSharedMemorySize, SMEM_DYN);

    prep_kernel<<<(XT + WT + 255) / 256, 256>>>(x, W1);
    gemm1_kernel<<<dim3(HID / TNT, BATCH / TMT), NTHR, SMEM_DYN>>>(b1, W2, b2, out);
}